// round 3
// baseline (speedup 1.0000x reference)
#include <cuda_runtime.h>
#include <cuda_bf16.h>
#include <math.h>

// Problem-size maxima (compile-time buffer sizing; runtime sizes passed as args)
#define NMAX 100000
#define EMAX 1600000
#define H 64

// ---------------------------------------------------------------------------
// Device scratch (allocation-free rule: __device__ globals)
// ---------------------------------------------------------------------------
__device__ float g_bufA[NMAX * H];   // 25.6 MB
__device__ float g_bufB[NMAX * H];   // 25.6 MB
__device__ int   g_cnt [NMAX];
__device__ int   g_fill[NMAX];
__device__ int   g_ptr [NMAX];
__device__ int   g_srow[EMAX];       // 6.4 MB
__device__ float g_dinv[NMAX];
__device__ int   g_bsum[256];
__device__ int   g_boff[256];
__device__ float g_enc_s[H], g_enc_t[H], g_ep_s[H], g_ep_t[H];

// ---------------------------------------------------------------------------
// Small setup kernels
// ---------------------------------------------------------------------------
__global__ void zero_kernel(int* cnt, int* fill, int n) {
    int i = blockIdx.x * blockDim.x + threadIdx.x;
    if (i < n) { cnt[i] = 0; fill[i] = 0; }
}

// Fold BN (+ preceding bias) into per-channel scale/shift:
//   bn(acc + b) = acc*s + t,  s = g*rsqrt(var+eps),  t = (b-mean)*s + beta
__global__ void prep_consts(const float* __restrict__ enc_b, const float* __restrict__ enc_g,
                            const float* __restrict__ enc_beta, const float* __restrict__ enc_mean,
                            const float* __restrict__ enc_var,
                            const float* __restrict__ ep1_b, const float* __restrict__ ep_g,
                            const float* __restrict__ ep_beta, const float* __restrict__ ep_mean,
                            const float* __restrict__ ep_var,
                            float* enc_s, float* enc_t, float* ep_s, float* ep_t) {
    int j = threadIdx.x;
    if (j < H) {
        float se = enc_g[j] * rsqrtf(enc_var[j] + 1e-5f);
        enc_s[j] = se;
        enc_t[j] = (enc_b[j] - enc_mean[j]) * se + enc_beta[j];
        float sp = ep_g[j] * rsqrtf(ep_var[j] + 1e-5f);
        ep_s[j] = sp;
        ep_t[j] = (ep1_b[j] - ep_mean[j]) * sp + ep_beta[j];
    }
}

__global__ void hist_kernel(const int* __restrict__ col, int* cnt, int e) {
    int i = blockIdx.x * blockDim.x + threadIdx.x;
    if (i < e) atomicAdd(&cnt[col[i]], 1);
}

__global__ void dinv_kernel(const int* __restrict__ cnt, float* dinv, int n) {
    int i = blockIdx.x * blockDim.x + threadIdx.x;
    if (i < n) dinv[i] = rsqrtf((float)(cnt[i] + 1));   // +1 = self loop; deg >= 1 always
}

// ---- 3-phase exclusive scan over cnt[] -> ptr[] ----
__global__ void scan1(const int* __restrict__ cnt, int* ptr, int* bsum, int n) {
    __shared__ int sh[1024];
    int t = threadIdx.x;
    int idx = blockIdx.x * 1024 + t;
    int v = (idx < n) ? cnt[idx] : 0;
    sh[t] = v;
    __syncthreads();
    #pragma unroll
    for (int o = 1; o < 1024; o <<= 1) {
        int x = (t >= o) ? sh[t - o] : 0;
        __syncthreads();
        sh[t] += x;
        __syncthreads();
    }
    if (idx < n) ptr[idx] = sh[t] - v;        // exclusive
    if (t == 1023) bsum[blockIdx.x] = sh[t];  // block total
}

__global__ void scan2(const int* __restrict__ bsum, int* boff, int nb) {
    __shared__ int sh[128];
    int t = threadIdx.x;
    int v = (t < nb) ? bsum[t] : 0;
    sh[t] = v;
    __syncthreads();
    #pragma unroll
    for (int o = 1; o < 128; o <<= 1) {
        int x = (t >= o) ? sh[t - o] : 0;
        __syncthreads();
        sh[t] += x;
        __syncthreads();
    }
    if (t < nb) boff[t] = sh[t] - v;          // exclusive
}

__global__ void scan3(int* ptr, const int* __restrict__ boff, int n) {
    int i = blockIdx.x * blockDim.x + threadIdx.x;
    if (i < n) ptr[i] += boff[i >> 10];
}

// CSR fill: bucket edges by destination node (col)
__global__ void fill_kernel(const int* __restrict__ row, const int* __restrict__ col,
                            const int* __restrict__ ptr, int* fill, int* srow, int e) {
    int i = blockIdx.x * blockDim.x + threadIdx.x;
    if (i >= e) return;
    int c = col[i];
    int pos = ptr[c] + atomicAdd(&fill[c], 1);
    srow[pos] = row[i];
}

// ---------------------------------------------------------------------------
// Register-tiled SIMT GEMM: out[M,64] = A[M,K] @ W[K,64]  (+ optional BN+ReLU)
// Block: 256 threads (16x16), TILE_M=64 rows, 4x4 register tile per thread.
// W fully staged in smem; A streamed in KC=32 chunks, stored k-major so the
// inner loop is 1 LDS.128 (A, 4 rows) + 1 LDS.128 (W, 4 cols) per 16 FMAs.
// ---------------------------------------------------------------------------
#define TILE_M 64
#define KC 32

template<int K, bool BNRELU>
__global__ void __launch_bounds__(256)
gemm64(const float* __restrict__ A, const float* __restrict__ W,
       float* __restrict__ out, const float* __restrict__ s,
       const float* __restrict__ t, int M) {
    __shared__ float wS[K][H];
    __shared__ float aS[KC][68];   // padded: conflict-free, 16B-aligned rows

    int tid = threadIdx.x;
    // Stage W (K*64 floats) via float4
    for (int i = tid; i < K * H / 4; i += 256)
        ((float4*)&wS[0][0])[i] = ((const float4*)W)[i];

    int ty = tid >> 4, tx = tid & 15;
    int rowBase = blockIdx.x * TILE_M;
    int r0 = ty * 4;   // local row base
    int cx = tx * 4;   // col base

    float acc[4][4];
    #pragma unroll
    for (int i = 0; i < 4; i++)
        #pragma unroll
        for (int j = 0; j < 4; j++) acc[i][j] = 0.f;

    for (int k0 = 0; k0 < K; k0 += KC) {
        __syncthreads();
        // Stage A chunk [64 rows][KC], transposed to aS[k][row]
        #pragma unroll
        for (int l = 0; l < 2; l++) {
            int li = tid + l * 256;        // 0..511  (512 float4 loads)
            int r  = li >> 3;              // 0..63
            int kq = (li & 7) * 4;         // 0,4,...,28
            int gr = rowBase + r;
            float4 v = make_float4(0.f, 0.f, 0.f, 0.f);
            if (gr < M) v = *(const float4*)&A[(size_t)gr * K + k0 + kq];
            aS[kq + 0][r] = v.x;
            aS[kq + 1][r] = v.y;
            aS[kq + 2][r] = v.z;
            aS[kq + 3][r] = v.w;
        }
        __syncthreads();
        #pragma unroll
        for (int kk = 0; kk < KC; kk++) {
            float4 af = *(const float4*)&aS[kk][r0];
            float4 wf = *(const float4*)&wS[k0 + kk][cx];
            float av[4] = {af.x, af.y, af.z, af.w};
            float wv[4] = {wf.x, wf.y, wf.z, wf.w};
            #pragma unroll
            for (int i = 0; i < 4; i++)
                #pragma unroll
                for (int j = 0; j < 4; j++)
                    acc[i][j] = fmaf(av[i], wv[j], acc[i][j]);
        }
    }

    float sv[4] = {1.f, 1.f, 1.f, 1.f}, tv[4] = {0.f, 0.f, 0.f, 0.f};
    if (BNRELU) {
        float4 s4 = *(const float4*)&s[cx];
        float4 t4 = *(const float4*)&t[cx];
        sv[0] = s4.x; sv[1] = s4.y; sv[2] = s4.z; sv[3] = s4.w;
        tv[0] = t4.x; tv[1] = t4.y; tv[2] = t4.z; tv[3] = t4.w;
    }
    #pragma unroll
    for (int i = 0; i < 4; i++) {
        int gr = rowBase + r0 + i;
        if (gr < M) {
            float4 o;
            float v0 = acc[i][0], v1 = acc[i][1], v2 = acc[i][2], v3 = acc[i][3];
            if (BNRELU) {
                v0 = fmaxf(fmaf(v0, sv[0], tv[0]), 0.f);
                v1 = fmaxf(fmaf(v1, sv[1], tv[1]), 0.f);
                v2 = fmaxf(fmaf(v2, sv[2], tv[2]), 0.f);
                v3 = fmaxf(fmaf(v3, sv[3], tv[3]), 0.f);
            }
            o.x = v0; o.y = v1; o.z = v2; o.w = v3;
            *(float4*)&out[(size_t)gr * H + cx] = o;
        }
    }
}

// ---------------------------------------------------------------------------
// GCN aggregation (atomic-free, CSR by destination):
//   out[c] = relu( (sum_{e: col=c} hw[row_e]*dinv[row_e] + hw[c]*dinv[c]) * dinv[c] + b )
// One warp per node; lane owns features {lane, lane+32}. Edge loop batched by 4
// for memory-level parallelism.
// ---------------------------------------------------------------------------
__global__ void __launch_bounds__(256)
aggregate_kernel(const float* __restrict__ hw, const int* __restrict__ ptr,
                 const int* __restrict__ cnt, const int* __restrict__ srow,
                 const float* __restrict__ dinv, const float* __restrict__ bias,
                 float* __restrict__ out, int n) {
    int warpId = (blockIdx.x * blockDim.x + threadIdx.x) >> 5;
    int lane = threadIdx.x & 31;
    if (warpId >= n) return;
    int nd = warpId;
    float dn = dinv[nd];
    // self loop (dn factored out of the outer multiply)
    float acc0 = hw[nd * H + lane]      * dn;
    float acc1 = hw[nd * H + 32 + lane] * dn;

    int st = ptr[nd], en = st + cnt[nd];
    int i = st;
    for (; i + 4 <= en; i += 4) {
        int r0 = srow[i], r1 = srow[i + 1], r2 = srow[i + 2], r3 = srow[i + 3];
        float w0 = dinv[r0], w1 = dinv[r1], w2 = dinv[r2], w3 = dinv[r3];
        float a0 = hw[r0 * H + lane],      b0 = hw[r0 * H + 32 + lane];
        float a1 = hw[r1 * H + lane],      b1 = hw[r1 * H + 32 + lane];
        float a2 = hw[r2 * H + lane],      b2 = hw[r2 * H + 32 + lane];
        float a3 = hw[r3 * H + lane],      b3 = hw[r3 * H + 32 + lane];
        acc0 = fmaf(a0, w0, acc0); acc1 = fmaf(b0, w0, acc1);
        acc0 = fmaf(a1, w1, acc0); acc1 = fmaf(b1, w1, acc1);
        acc0 = fmaf(a2, w2, acc0); acc1 = fmaf(b2, w2, acc1);
        acc0 = fmaf(a3, w3, acc0); acc1 = fmaf(b3, w3, acc1);
    }
    for (; i < en; i++) {
        int r = srow[i];
        float w = dinv[r];
        acc0 = fmaf(hw[r * H + lane],      w, acc0);
        acc1 = fmaf(hw[r * H + 32 + lane], w, acc1);
    }
    float v0 = fmaxf(fmaf(acc0, dn, bias[lane]),      0.f);
    float v1 = fmaxf(fmaf(acc1, dn, bias[lane + 32]), 0.f);
    out[nd * H + lane]      = v0;
    out[nd * H + 32 + lane] = v1;
}

// ---------------------------------------------------------------------------
// Edge predictor: per edge  z = Pr[row] + Pc[col];  a = relu(z*s + t);
//                 pred = sigmoid(dot(a, w2) + b2)
// One warp per edge (grid-stride); per-channel constants register-resident.
// ---------------------------------------------------------------------------
__global__ void __launch_bounds__(256)
edge_kernel(const float* __restrict__ Pr, const float* __restrict__ Pc,
            const int* __restrict__ row, const int* __restrict__ col,
            const float* __restrict__ s, const float* __restrict__ t,
            const float* __restrict__ w2, const float* __restrict__ b2,
            float* __restrict__ out, int e) {
    int lane = threadIdx.x & 31;
    int warp = (blockIdx.x * blockDim.x + threadIdx.x) >> 5;
    int nwarps = (gridDim.x * blockDim.x) >> 5;

    float s0 = s[lane], s1 = s[lane + 32];
    float t0 = t[lane], t1 = t[lane + 32];
    float u0 = w2[lane], u1 = w2[lane + 32];
    float bb = b2[0];

    for (int ei = warp; ei < e; ei += nwarps) {
        int r = row[ei], c = col[ei];
        float z0 = Pr[r * H + lane]      + Pc[c * H + lane];
        float z1 = Pr[r * H + 32 + lane] + Pc[c * H + 32 + lane];
        float a0 = fmaxf(fmaf(z0, s0, t0), 0.f);
        float a1 = fmaxf(fmaf(z1, s1, t1), 0.f);
        float p = fmaf(a1, u1, a0 * u0);
        #pragma unroll
        for (int o = 16; o > 0; o >>= 1)
            p += __shfl_down_sync(0xffffffffu, p, o);
        if (lane == 0)
            out[ei] = 1.f / (1.f + __expf(-(p + bb)));
    }
}

// ---------------------------------------------------------------------------
// Launch sequence (all default stream; graph-capturable, allocation-free)
// ---------------------------------------------------------------------------
extern "C" void kernel_launch(void* const* d_in, const int* in_sizes, int n_in,
                              void* d_out, int out_size) {
    const float* x        = (const float*)d_in[0];
    const int*   eidx     = (const int*)  d_in[1];
    const float* enc_W    = (const float*)d_in[2];
    const float* enc_b    = (const float*)d_in[3];
    const float* enc_g    = (const float*)d_in[4];
    const float* enc_beta = (const float*)d_in[5];
    const float* enc_mean = (const float*)d_in[6];
    const float* enc_var  = (const float*)d_in[7];
    const float* conv1_W  = (const float*)d_in[8];
    const float* conv1_b  = (const float*)d_in[9];
    const float* conv2_W  = (const float*)d_in[10];
    const float* conv2_b  = (const float*)d_in[11];
    const float* ep1_W    = (const float*)d_in[12];
    const float* ep1_b    = (const float*)d_in[13];
    const float* ep_g     = (const float*)d_in[14];
    const float* ep_beta  = (const float*)d_in[15];
    const float* ep_mean  = (const float*)d_in[16];
    const float* ep_var   = (const float*)d_in[17];
    const float* ep2_W    = (const float*)d_in[18];
    const float* ep2_b    = (const float*)d_in[19];

    int n = in_sizes[0] / 128;   // nodes
    int e = in_sizes[1] / 2;     // edges
    const int* row = eidx;
    const int* col = eidx + e;
    float* out = (float*)d_out;

    // Resolve scratch symbols (pure lookups; capture-safe)
    float *bufA, *bufB, *dinv, *enc_s, *enc_t, *ep_s, *ep_t;
    int *cnt, *fill, *ptr, *srow, *bsum, *boff;
    cudaGetSymbolAddress((void**)&bufA, g_bufA);
    cudaGetSymbolAddress((void**)&bufB, g_bufB);
    cudaGetSymbolAddress((void**)&cnt,  g_cnt);
    cudaGetSymbolAddress((void**)&fill, g_fill);
    cudaGetSymbolAddress((void**)&ptr,  g_ptr);
    cudaGetSymbolAddress((void**)&srow, g_srow);
    cudaGetSymbolAddress((void**)&dinv, g_dinv);
    cudaGetSymbolAddress((void**)&bsum, g_bsum);
    cudaGetSymbolAddress((void**)&boff, g_boff);
    cudaGetSymbolAddress((void**)&enc_s, g_enc_s);
    cudaGetSymbolAddress((void**)&enc_t, g_enc_t);
    cudaGetSymbolAddress((void**)&ep_s, g_ep_s);
    cudaGetSymbolAddress((void**)&ep_t, g_ep_t);

    int nB256 = (n + 255) / 256;
    int eB256 = (e + 255) / 256;
    int nb    = (n + 1023) / 1024;
    int gemmB = (n + TILE_M - 1) / TILE_M;

    // --- graph structure setup ---
    zero_kernel<<<nB256, 256>>>(cnt, fill, n);
    prep_consts<<<1, 64>>>(enc_b, enc_g, enc_beta, enc_mean, enc_var,
                           ep1_b, ep_g, ep_beta, ep_mean, ep_var,
                           enc_s, enc_t, ep_s, ep_t);
    hist_kernel<<<eB256, 256>>>(col, cnt, e);
    dinv_kernel<<<nB256, 256>>>(cnt, dinv, n);
    scan1<<<nb, 1024>>>(cnt, ptr, bsum, n);
    scan2<<<1, 128>>>(bsum, boff, nb);
    scan3<<<nB256, 256>>>(ptr, boff, n);
    fill_kernel<<<eB256, 256>>>(row, col, ptr, fill, srow, e);

    // --- node pipeline ---
    // h0 = relu(bn(x @ enc_W + b))          -> bufA
    gemm64<128, true><<<gemmB, 256>>>(x, enc_W, bufA, enc_s, enc_t, n);
    // hw1 = h0 @ conv1_W                     -> bufB
    gemm64<64, false><<<gemmB, 256>>>(bufA, conv1_W, bufB, nullptr, nullptr, n);
    // h1 = relu(aggregate(hw1) + b1)         -> bufA
    aggregate_kernel<<<(n * 32 + 255) / 256, 256>>>(bufB, ptr, cnt, srow, dinv, conv1_b, bufA, n);
    // hw2 = h1 @ conv2_W                     -> bufB
    gemm64<64, false><<<gemmB, 256>>>(bufA, conv2_W, bufB, nullptr, nullptr, n);
    // h2 = relu(aggregate(hw2) + b2)         -> d_out[0 : n*64]  (node_embeddings)
    aggregate_kernel<<<(n * 32 + 255) / 256, 256>>>(bufB, ptr, cnt, srow, dinv, conv2_b, out, n);

    // --- edge predictor (restructured) ---
    // Pr = h2 @ ep1_W[0:64]   -> bufA ;  Pc = h2 @ ep1_W[64:128] -> bufB
    gemm64<64, false><<<gemmB, 256>>>(out, ep1_W,            bufA, nullptr, nullptr, n);
    gemm64<64, false><<<gemmB, 256>>>(out, ep1_W + 64 * H,   bufB, nullptr, nullptr, n);
    // pred[e] = sigmoid(dot(relu((Pr[row]+Pc[col])*s + t), w2) + b2) -> d_out[n*64 : ]
    edge_kernel<<<1184, 256>>>(bufA, bufB, row, col, ep_s, ep_t, ep2_W, ep2_b,
                               out + (size_t)n * H, e);
}

// round 4
// speedup vs baseline: 1.0096x; 1.0096x over previous
#include <cuda_runtime.h>
#include <cuda_bf16.h>
#include <math.h>

// Problem-size maxima (compile-time buffer sizing; runtime sizes passed as args)
#define NMAX 100000
#define EMAX 1600000
#define H 64

// ---------------------------------------------------------------------------
// Device scratch (allocation-free rule: __device__ globals)
// ---------------------------------------------------------------------------
__device__ float g_bufA[NMAX * H];   // 25.6 MB
__device__ float g_bufB[NMAX * H];   // 25.6 MB
__device__ int   g_cnt [NMAX];
__device__ int   g_fill[NMAX];
__device__ int   g_ptr [NMAX];
__device__ int   g_srow[EMAX];       // 6.4 MB
__device__ float g_dinv[NMAX];
__device__ int   g_bsum[256];
__device__ int   g_boff[256];
__device__ float g_enc_s[H], g_enc_t[H], g_ep_s[H], g_ep_t[H];

// ---------------------------------------------------------------------------
// Small setup kernels
// ---------------------------------------------------------------------------
__global__ void zero_kernel(int* cnt, int* fill, int n) {
    int i = blockIdx.x * blockDim.x + threadIdx.x;
    if (i < n) { cnt[i] = 0; fill[i] = 0; }
}

// Fold BN (+ preceding bias) into per-channel scale/shift:
//   bn(acc + b) = acc*s + t,  s = g*rsqrt(var+eps),  t = (b-mean)*s + beta
__global__ void prep_consts(const float* __restrict__ enc_b, const float* __restrict__ enc_g,
                            const float* __restrict__ enc_beta, const float* __restrict__ enc_mean,
                            const float* __restrict__ enc_var,
                            const float* __restrict__ ep1_b, const float* __restrict__ ep_g,
                            const float* __restrict__ ep_beta, const float* __restrict__ ep_mean,
                            const float* __restrict__ ep_var,
                            float* enc_s, float* enc_t, float* ep_s, float* ep_t) {
    int j = threadIdx.x;
    if (j < H) {
        float se = enc_g[j] * rsqrtf(enc_var[j] + 1e-5f);
        enc_s[j] = se;
        enc_t[j] = (enc_b[j] - enc_mean[j]) * se + enc_beta[j];
        float sp = ep_g[j] * rsqrtf(ep_var[j] + 1e-5f);
        ep_s[j] = sp;
        ep_t[j] = (ep1_b[j] - ep_mean[j]) * sp + ep_beta[j];
    }
}

__global__ void hist_kernel(const int* __restrict__ col, int* cnt, int e) {
    int i = blockIdx.x * blockDim.x + threadIdx.x;
    if (i < e) atomicAdd(&cnt[col[i]], 1);
}

__global__ void dinv_kernel(const int* __restrict__ cnt, float* dinv, int n) {
    int i = blockIdx.x * blockDim.x + threadIdx.x;
    if (i < n) dinv[i] = rsqrtf((float)(cnt[i] + 1));   // +1 = self loop; deg >= 1 always
}

// ---- 3-phase exclusive scan over cnt[] -> ptr[] ----
__global__ void scan1(const int* __restrict__ cnt, int* ptr, int* bsum, int n) {
    __shared__ int sh[1024];
    int t = threadIdx.x;
    int idx = blockIdx.x * 1024 + t;
    int v = (idx < n) ? cnt[idx] : 0;
    sh[t] = v;
    __syncthreads();
    #pragma unroll
    for (int o = 1; o < 1024; o <<= 1) {
        int x = (t >= o) ? sh[t - o] : 0;
        __syncthreads();
        sh[t] += x;
        __syncthreads();
    }
    if (idx < n) ptr[idx] = sh[t] - v;        // exclusive
    if (t == 1023) bsum[blockIdx.x] = sh[t];  // block total
}

__global__ void scan2(const int* __restrict__ bsum, int* boff, int nb) {
    __shared__ int sh[128];
    int t = threadIdx.x;
    int v = (t < nb) ? bsum[t] : 0;
    sh[t] = v;
    __syncthreads();
    #pragma unroll
    for (int o = 1; o < 128; o <<= 1) {
        int x = (t >= o) ? sh[t - o] : 0;
        __syncthreads();
        sh[t] += x;
        __syncthreads();
    }
    if (t < nb) boff[t] = sh[t] - v;          // exclusive
}

__global__ void scan3(int* ptr, const int* __restrict__ boff, int n) {
    int i = blockIdx.x * blockDim.x + threadIdx.x;
    if (i < n) ptr[i] += boff[i >> 10];
}

// CSR fill: bucket edges by destination node (col)
__global__ void fill_kernel(const int* __restrict__ row, const int* __restrict__ col,
                            const int* __restrict__ ptr, int* fill, int* srow, int e) {
    int i = blockIdx.x * blockDim.x + threadIdx.x;
    if (i >= e) return;
    int c = col[i];
    int pos = ptr[c] + atomicAdd(&fill[c], 1);
    srow[pos] = row[i];
}

// ---------------------------------------------------------------------------
// Register-tiled SIMT GEMM: out[M,64] = A[M,K] @ W[K,64]  (+ optional BN+ReLU)
// Block: 256 threads (16x16), TILE_M=64 rows, 4x4 register tile per thread.
// W fully staged in smem; A streamed in KC=32 chunks, stored k-major so the
// inner loop is 1 LDS.128 (A, 4 rows) + 1 LDS.128 (W, 4 cols) per 16 FMAs.
// ---------------------------------------------------------------------------
#define TILE_M 64
#define KC 32

template<int K, bool BNRELU>
__global__ void __launch_bounds__(256)
gemm64(const float* __restrict__ A, const float* __restrict__ W,
       float* __restrict__ out, const float* __restrict__ s,
       const float* __restrict__ t, int M) {
    __shared__ float wS[K][H];
    __shared__ float aS[KC][68];   // padded: conflict-free, 16B-aligned rows

    int tid = threadIdx.x;
    // Stage W (K*64 floats) via float4
    for (int i = tid; i < K * H / 4; i += 256)
        ((float4*)&wS[0][0])[i] = ((const float4*)W)[i];

    int ty = tid >> 4, tx = tid & 15;
    int rowBase = blockIdx.x * TILE_M;
    int r0 = ty * 4;   // local row base
    int cx = tx * 4;   // col base

    float acc[4][4];
    #pragma unroll
    for (int i = 0; i < 4; i++)
        #pragma unroll
        for (int j = 0; j < 4; j++) acc[i][j] = 0.f;

    for (int k0 = 0; k0 < K; k0 += KC) {
        __syncthreads();
        // Stage A chunk [64 rows][KC], transposed to aS[k][row]
        #pragma unroll
        for (int l = 0; l < 2; l++) {
            int li = tid + l * 256;        // 0..511  (512 float4 loads)
            int r  = li >> 3;              // 0..63
            int kq = (li & 7) * 4;         // 0,4,...,28
            int gr = rowBase + r;
            float4 v = make_float4(0.f, 0.f, 0.f, 0.f);
            if (gr < M) v = *(const float4*)&A[(size_t)gr * K + k0 + kq];
            aS[kq + 0][r] = v.x;
            aS[kq + 1][r] = v.y;
            aS[kq + 2][r] = v.z;
            aS[kq + 3][r] = v.w;
        }
        __syncthreads();
        #pragma unroll
        for (int kk = 0; kk < KC; kk++) {
            float4 af = *(const float4*)&aS[kk][r0];
            float4 wf = *(const float4*)&wS[k0 + kk][cx];
            float av[4] = {af.x, af.y, af.z, af.w};
            float wv[4] = {wf.x, wf.y, wf.z, wf.w};
            #pragma unroll
            for (int i = 0; i < 4; i++)
                #pragma unroll
                for (int j = 0; j < 4; j++)
                    acc[i][j] = fmaf(av[i], wv[j], acc[i][j]);
        }
    }

    float sv[4] = {1.f, 1.f, 1.f, 1.f}, tv[4] = {0.f, 0.f, 0.f, 0.f};
    if (BNRELU) {
        float4 s4 = *(const float4*)&s[cx];
        float4 t4 = *(const float4*)&t[cx];
        sv[0] = s4.x; sv[1] = s4.y; sv[2] = s4.z; sv[3] = s4.w;
        tv[0] = t4.x; tv[1] = t4.y; tv[2] = t4.z; tv[3] = t4.w;
    }
    #pragma unroll
    for (int i = 0; i < 4; i++) {
        int gr = rowBase + r0 + i;
        if (gr < M) {
            float4 o;
            float v0 = acc[i][0], v1 = acc[i][1], v2 = acc[i][2], v3 = acc[i][3];
            if (BNRELU) {
                v0 = fmaxf(fmaf(v0, sv[0], tv[0]), 0.f);
                v1 = fmaxf(fmaf(v1, sv[1], tv[1]), 0.f);
                v2 = fmaxf(fmaf(v2, sv[2], tv[2]), 0.f);
                v3 = fmaxf(fmaf(v3, sv[3], tv[3]), 0.f);
            }
            o.x = v0; o.y = v1; o.z = v2; o.w = v3;
            *(float4*)&out[(size_t)gr * H + cx] = o;
        }
    }
}

// ---------------------------------------------------------------------------
// GCN aggregation (atomic-free, CSR by destination):
//   out[c] = relu( (sum_{e: col=c} hw[row_e]*dinv[row_e] + hw[c]*dinv[c]) * dinv[c] + b )
// One warp per node; lane owns features {lane, lane+32}. Edge loop batched by 4
// for memory-level parallelism.
// ---------------------------------------------------------------------------
__global__ void __launch_bounds__(256)
aggregate_kernel(const float* __restrict__ hw, const int* __restrict__ ptr,
                 const int* __restrict__ cnt, const int* __restrict__ srow,
                 const float* __restrict__ dinv, const float* __restrict__ bias,
                 float* __restrict__ out, int n) {
    int warpId = (blockIdx.x * blockDim.x + threadIdx.x) >> 5;
    int lane = threadIdx.x & 31;
    if (warpId >= n) return;
    int nd = warpId;
    float dn = dinv[nd];
    // self loop (dn factored out of the outer multiply)
    float acc0 = hw[nd * H + lane]      * dn;
    float acc1 = hw[nd * H + 32 + lane] * dn;

    int st = ptr[nd], en = st + cnt[nd];
    int i = st;
    for (; i + 4 <= en; i += 4) {
        int r0 = srow[i], r1 = srow[i + 1], r2 = srow[i + 2], r3 = srow[i + 3];
        float w0 = dinv[r0], w1 = dinv[r1], w2 = dinv[r2], w3 = dinv[r3];
        float a0 = hw[r0 * H + lane],      b0 = hw[r0 * H + 32 + lane];
        float a1 = hw[r1 * H + lane],      b1 = hw[r1 * H + 32 + lane];
        float a2 = hw[r2 * H + lane],      b2 = hw[r2 * H + 32 + lane];
        float a3 = hw[r3 * H + lane],      b3 = hw[r3 * H + 32 + lane];
        acc0 = fmaf(a0, w0, acc0); acc1 = fmaf(b0, w0, acc1);
        acc0 = fmaf(a1, w1, acc0); acc1 = fmaf(b1, w1, acc1);
        acc0 = fmaf(a2, w2, acc0); acc1 = fmaf(b2, w2, acc1);
        acc0 = fmaf(a3, w3, acc0); acc1 = fmaf(b3, w3, acc1);
    }
    for (; i < en; i++) {
        int r = srow[i];
        float w = dinv[r];
        acc0 = fmaf(hw[r * H + lane],      w, acc0);
        acc1 = fmaf(hw[r * H + 32 + lane], w, acc1);
    }
    float v0 = fmaxf(fmaf(acc0, dn, bias[lane]),      0.f);
    float v1 = fmaxf(fmaf(acc1, dn, bias[lane + 32]), 0.f);
    out[nd * H + lane]      = v0;
    out[nd * H + 32 + lane] = v1;
}

// ---------------------------------------------------------------------------
// Edge predictor: per edge  z = Pr[row] + Pc[col];  a = relu(z*s + t);
//                 pred = sigmoid(dot(a, w2) + b2)
// One warp per edge (grid-stride); per-channel constants register-resident.
// ---------------------------------------------------------------------------
__global__ void __launch_bounds__(256)
edge_kernel(const float* __restrict__ Pr, const float* __restrict__ Pc,
            const int* __restrict__ row, const int* __restrict__ col,
            const float* __restrict__ s, const float* __restrict__ t,
            const float* __restrict__ w2, const float* __restrict__ b2,
            float* __restrict__ out, int e) {
    int lane = threadIdx.x & 31;
    int warp = (blockIdx.x * blockDim.x + threadIdx.x) >> 5;
    int nwarps = (gridDim.x * blockDim.x) >> 5;

    float s0 = s[lane], s1 = s[lane + 32];
    float t0 = t[lane], t1 = t[lane + 32];
    float u0 = w2[lane], u1 = w2[lane + 32];
    float bb = b2[0];

    for (int ei = warp; ei < e; ei += nwarps) {
        int r = row[ei], c = col[ei];
        float z0 = Pr[r * H + lane]      + Pc[c * H + lane];
        float z1 = Pr[r * H + 32 + lane] + Pc[c * H + 32 + lane];
        float a0 = fmaxf(fmaf(z0, s0, t0), 0.f);
        float a1 = fmaxf(fmaf(z1, s1, t1), 0.f);
        float p = fmaf(a1, u1, a0 * u0);
        #pragma unroll
        for (int o = 16; o > 0; o >>= 1)
            p += __shfl_down_sync(0xffffffffu, p, o);
        if (lane == 0)
            out[ei] = 1.f / (1.f + __expf(-(p + bb)));
    }
}

// ---------------------------------------------------------------------------
// Launch sequence (all default stream; graph-capturable, allocation-free)
// ---------------------------------------------------------------------------
extern "C" void kernel_launch(void* const* d_in, const int* in_sizes, int n_in,
                              void* d_out, int out_size) {
    const float* x        = (const float*)d_in[0];
    const int*   eidx     = (const int*)  d_in[1];
    const float* enc_W    = (const float*)d_in[2];
    const float* enc_b    = (const float*)d_in[3];
    const float* enc_g    = (const float*)d_in[4];
    const float* enc_beta = (const float*)d_in[5];
    const float* enc_mean = (const float*)d_in[6];
    const float* enc_var  = (const float*)d_in[7];
    const float* conv1_W  = (const float*)d_in[8];
    const float* conv1_b  = (const float*)d_in[9];
    const float* conv2_W  = (const float*)d_in[10];
    const float* conv2_b  = (const float*)d_in[11];
    const float* ep1_W    = (const float*)d_in[12];
    const float* ep1_b    = (const float*)d_in[13];
    const float* ep_g     = (const float*)d_in[14];
    const float* ep_beta  = (const float*)d_in[15];
    const float* ep_mean  = (const float*)d_in[16];
    const float* ep_var   = (const float*)d_in[17];
    const float* ep2_W    = (const float*)d_in[18];
    const float* ep2_b    = (const float*)d_in[19];

    int n = in_sizes[0] / 128;   // nodes
    int e = in_sizes[1] / 2;     // edges
    const int* row = eidx;
    const int* col = eidx + e;
    float* out = (float*)d_out;

    // Resolve scratch symbols (pure lookups; capture-safe)
    float *bufA, *bufB, *dinv, *enc_s, *enc_t, *ep_s, *ep_t;
    int *cnt, *fill, *ptr, *srow, *bsum, *boff;
    cudaGetSymbolAddress((void**)&bufA, g_bufA);
    cudaGetSymbolAddress((void**)&bufB, g_bufB);
    cudaGetSymbolAddress((void**)&cnt,  g_cnt);
    cudaGetSymbolAddress((void**)&fill, g_fill);
    cudaGetSymbolAddress((void**)&ptr,  g_ptr);
    cudaGetSymbolAddress((void**)&srow, g_srow);
    cudaGetSymbolAddress((void**)&dinv, g_dinv);
    cudaGetSymbolAddress((void**)&bsum, g_bsum);
    cudaGetSymbolAddress((void**)&boff, g_boff);
    cudaGetSymbolAddress((void**)&enc_s, g_enc_s);
    cudaGetSymbolAddress((void**)&enc_t, g_enc_t);
    cudaGetSymbolAddress((void**)&ep_s, g_ep_s);
    cudaGetSymbolAddress((void**)&ep_t, g_ep_t);

    int nB256 = (n + 255) / 256;
    int eB256 = (e + 255) / 256;
    int nb    = (n + 1023) / 1024;
    int gemmB = (n + TILE_M - 1) / TILE_M;

    // --- graph structure setup ---
    zero_kernel<<<nB256, 256>>>(cnt, fill, n);
    prep_consts<<<1, 64>>>(enc_b, enc_g, enc_beta, enc_mean, enc_var,
                           ep1_b, ep_g, ep_beta, ep_mean, ep_var,
                           enc_s, enc_t, ep_s, ep_t);
    hist_kernel<<<eB256, 256>>>(col, cnt, e);
    dinv_kernel<<<nB256, 256>>>(cnt, dinv, n);
    scan1<<<nb, 1024>>>(cnt, ptr, bsum, n);
    scan2<<<1, 128>>>(bsum, boff, nb);
    scan3<<<nB256, 256>>>(ptr, boff, n);
    fill_kernel<<<eB256, 256>>>(row, col, ptr, fill, srow, e);

    // --- node pipeline ---
    // h0 = relu(bn(x @ enc_W + b))          -> bufA
    gemm64<128, true><<<gemmB, 256>>>(x, enc_W, bufA, enc_s, enc_t, n);
    // hw1 = h0 @ conv1_W                     -> bufB
    gemm64<64, false><<<gemmB, 256>>>(bufA, conv1_W, bufB, nullptr, nullptr, n);
    // h1 = relu(aggregate(hw1) + b1)         -> bufA
    aggregate_kernel<<<(n * 32 + 255) / 256, 256>>>(bufB, ptr, cnt, srow, dinv, conv1_b, bufA, n);
    // hw2 = h1 @ conv2_W                     -> bufB
    gemm64<64, false><<<gemmB, 256>>>(bufA, conv2_W, bufB, nullptr, nullptr, n);
    // h2 = relu(aggregate(hw2) + b2)         -> d_out[0 : n*64]  (node_embeddings)
    aggregate_kernel<<<(n * 32 + 255) / 256, 256>>>(bufB, ptr, cnt, srow, dinv, conv2_b, out, n);

    // --- edge predictor (restructured) ---
    // Pr = h2 @ ep1_W[0:64]   -> bufA ;  Pc = h2 @ ep1_W[64:128] -> bufB
    gemm64<64, false><<<gemmB, 256>>>(out, ep1_W,            bufA, nullptr, nullptr, n);
    gemm64<64, false><<<gemmB, 256>>>(out, ep1_W + 64 * H,   bufB, nullptr, nullptr, n);
    // pred[e] = sigmoid(dot(relu((Pr[row]+Pc[col])*s + t), w2) + b2) -> d_out[n*64 : ]
    edge_kernel<<<1184, 256>>>(bufA, bufB, row, col, ep_s, ep_t, ep2_W, ep2_b,
                               out + (size_t)n * H, e);
}

// round 5
// speedup vs baseline: 1.0791x; 1.0689x over previous
#include <cuda_runtime.h>
#include <cuda_bf16.h>
#include <math.h>

// Problem-size maxima (compile-time buffer sizing; runtime sizes passed as args)
#define NMAX 100000
#define EMAX 1600000
#define H 64

// ---------------------------------------------------------------------------
// Device scratch (allocation-free rule: __device__ globals)
// ---------------------------------------------------------------------------
__device__ float g_bufA[NMAX * H];   // 25.6 MB
__device__ float g_bufB[NMAX * H];   // 25.6 MB
__device__ int   g_cnt [NMAX];
__device__ int   g_fill[NMAX];
__device__ int   g_ptr [NMAX];
__device__ int   g_srow[EMAX];       // 6.4 MB
__device__ float g_dinv[NMAX];
__device__ int   g_bsum[256];
__device__ int   g_boff[256];
__device__ float g_enc_s[H], g_enc_t[H], g_ep_s[H], g_ep_t[H];

// ---------------------------------------------------------------------------
// Small setup kernels
// ---------------------------------------------------------------------------
__global__ void zero_kernel(int* cnt, int* fill, int n) {
    int i = blockIdx.x * blockDim.x + threadIdx.x;
    if (i < n) { cnt[i] = 0; fill[i] = 0; }
}

// Fold BN (+ preceding bias) into per-channel scale/shift:
//   bn(acc + b) = acc*s + t,  s = g*rsqrt(var+eps),  t = (b-mean)*s + beta
__global__ void prep_consts(const float* __restrict__ enc_b, const float* __restrict__ enc_g,
                            const float* __restrict__ enc_beta, const float* __restrict__ enc_mean,
                            const float* __restrict__ enc_var,
                            const float* __restrict__ ep1_b, const float* __restrict__ ep_g,
                            const float* __restrict__ ep_beta, const float* __restrict__ ep_mean,
                            const float* __restrict__ ep_var,
                            float* enc_s, float* enc_t, float* ep_s, float* ep_t) {
    int j = threadIdx.x;
    if (j < H) {
        float se = enc_g[j] * rsqrtf(enc_var[j] + 1e-5f);
        enc_s[j] = se;
        enc_t[j] = (enc_b[j] - enc_mean[j]) * se + enc_beta[j];
        float sp = ep_g[j] * rsqrtf(ep_var[j] + 1e-5f);
        ep_s[j] = sp;
        ep_t[j] = (ep1_b[j] - ep_mean[j]) * sp + ep_beta[j];
    }
}

__global__ void hist_kernel(const int* __restrict__ col, int* cnt, int e) {
    int i = blockIdx.x * blockDim.x + threadIdx.x;
    if (i < e) atomicAdd(&cnt[col[i]], 1);
}

// ---- 3-phase exclusive scan over cnt[] -> ptr[]  (also emits dinv) ----
__global__ void scan1(const int* __restrict__ cnt, int* ptr, int* bsum,
                      float* __restrict__ dinv, int n) {
    __shared__ int sh[1024];
    int t = threadIdx.x;
    int idx = blockIdx.x * 1024 + t;
    int v = (idx < n) ? cnt[idx] : 0;
    if (idx < n) dinv[idx] = rsqrtf((float)(v + 1));   // +1 = self loop; deg >= 1
    sh[t] = v;
    __syncthreads();
    #pragma unroll
    for (int o = 1; o < 1024; o <<= 1) {
        int x = (t >= o) ? sh[t - o] : 0;
        __syncthreads();
        sh[t] += x;
        __syncthreads();
    }
    if (idx < n) ptr[idx] = sh[t] - v;        // exclusive
    if (t == 1023) bsum[blockIdx.x] = sh[t];  // block total
}

__global__ void scan2(const int* __restrict__ bsum, int* boff, int nb) {
    __shared__ int sh[128];
    int t = threadIdx.x;
    int v = (t < nb) ? bsum[t] : 0;
    sh[t] = v;
    __syncthreads();
    #pragma unroll
    for (int o = 1; o < 128; o <<= 1) {
        int x = (t >= o) ? sh[t - o] : 0;
        __syncthreads();
        sh[t] += x;
        __syncthreads();
    }
    if (t < nb) boff[t] = sh[t] - v;          // exclusive
}

__global__ void scan3(int* ptr, const int* __restrict__ boff, int n) {
    int i = blockIdx.x * blockDim.x + threadIdx.x;
    if (i < n) ptr[i] += boff[i >> 10];
}

// CSR fill: bucket edges by destination node (col)
__global__ void fill_kernel(const int* __restrict__ row, const int* __restrict__ col,
                            const int* __restrict__ ptr, int* fill, int* srow, int e) {
    int i = blockIdx.x * blockDim.x + threadIdx.x;
    if (i >= e) return;
    int c = col[i];
    int pos = ptr[c] + atomicAdd(&fill[c], 1);
    srow[pos] = row[i];
}

// ---------------------------------------------------------------------------
// tf32 tensor-core GEMM with 3xTF32 precision split
//   out[M,64] = A[M,K] @ W[K,64]  (+ optional folded BN+ReLU)
// Block: 256 threads / 8 warps, tile 128(M) x 64(N), K chunked by 16.
// Warp (wm=warp>>1, wn=warp&1) owns 32x32: 2 m-tiles x 4 n-tiles of m16n8k8.
// A and W are pre-split into (hi, lo) tf32 parts in smem; per product:
//   A*B ~= Ahi*Bhi + Alo*Bhi + Ahi*Blo   (dropped Alo*Blo ~ 2^-22 rel)
// Smem layouts padded to 20 words/row -> conflict-free fragment LDS.
// ---------------------------------------------------------------------------
__device__ __forceinline__ unsigned f2tf32(float x) {
    unsigned r;
    asm("cvt.rna.tf32.f32 %0, %1;" : "=r"(r) : "f"(x));
    return r;
}
__device__ __forceinline__ void split_tf32(float x, unsigned& hi, unsigned& lo) {
    hi = f2tf32(x);
    lo = f2tf32(x - __uint_as_float(hi));
}
__device__ __forceinline__ void mma_tf32(float c[4],
                                         unsigned a0, unsigned a1, unsigned a2, unsigned a3,
                                         unsigned b0, unsigned b1) {
    asm volatile("mma.sync.aligned.m16n8k8.row.col.f32.tf32.tf32.f32 "
                 "{%0,%1,%2,%3}, {%4,%5,%6,%7}, {%8,%9}, {%0,%1,%2,%3};"
                 : "+f"(c[0]), "+f"(c[1]), "+f"(c[2]), "+f"(c[3])
                 : "r"(a0), "r"(a1), "r"(a2), "r"(a3), "r"(b0), "r"(b1));
}

#define GTM 128   // rows per block
#define GKC 16    // K chunk

template<int K, bool BNRELU>
__global__ void __launch_bounds__(256)
gemm_tc(const float* __restrict__ A, const float* __restrict__ W,
        float* __restrict__ out, const float* __restrict__ s,
        const float* __restrict__ t, int M) {
    __shared__ unsigned aHi[GTM][20], aLo[GTM][20];   // [row][k], pad 20
    __shared__ unsigned wHiT[64][20], wLoT[64][20];   // [n][k],  pad 20

    const int tid  = threadIdx.x;
    const int lane = tid & 31;
    const int warp = tid >> 5;
    const int g = lane >> 2, tt = lane & 3;
    const int rm = (warp >> 1) * 32;          // warp row base (0,32,64,96)
    const int cn = (warp & 1) * 32;           // warp col base (0,32)
    const int rowBase = blockIdx.x * GTM;

    float acc[2][4][4];
    #pragma unroll
    for (int a = 0; a < 2; a++)
        #pragma unroll
        for (int b = 0; b < 4; b++)
            #pragma unroll
            for (int c = 0; c < 4; c++) acc[a][b][c] = 0.f;

    for (int k0 = 0; k0 < K; k0 += GKC) {
        __syncthreads();
        // ---- stage A chunk [128 rows][16 k] split hi/lo ----
        #pragma unroll
        for (int it = 0; it < 2; it++) {
            int li = tid + it * 256;          // 0..511
            int r  = li >> 2;                 // 0..127
            int kq = (li & 3) * 4;            // 0,4,8,12
            int gr = rowBase + r;
            float4 v = make_float4(0.f, 0.f, 0.f, 0.f);
            if (gr < M) v = *(const float4*)&A[(size_t)gr * K + k0 + kq];
            unsigned h0, l0, h1, l1, h2, l2, h3, l3;
            split_tf32(v.x, h0, l0); split_tf32(v.y, h1, l1);
            split_tf32(v.z, h2, l2); split_tf32(v.w, h3, l3);
            *(uint4*)&aHi[r][kq] = make_uint4(h0, h1, h2, h3);
            *(uint4*)&aLo[r][kq] = make_uint4(l0, l1, l2, l3);
        }
        // ---- stage W chunk [16 k][64 n], transposed to [n][k], split ----
        {
            int k  = tid >> 4;                // 0..15
            int nq = (tid & 15) * 4;          // 0..60
            float4 v = *(const float4*)&W[(size_t)(k0 + k) * H + nq];
            unsigned h, l;
            split_tf32(v.x, h, l); wHiT[nq + 0][k] = h; wLoT[nq + 0][k] = l;
            split_tf32(v.y, h, l); wHiT[nq + 1][k] = h; wLoT[nq + 1][k] = l;
            split_tf32(v.z, h, l); wHiT[nq + 2][k] = h; wLoT[nq + 2][k] = l;
            split_tf32(v.w, h, l); wHiT[nq + 3][k] = h; wLoT[nq + 3][k] = l;
        }
        __syncthreads();

        #pragma unroll
        for (int kk = 0; kk < GKC; kk += 8) {
            unsigned ah[2][4], al[2][4];
            #pragma unroll
            for (int mt = 0; mt < 2; mt++) {
                int rb = rm + mt * 16;
                ah[mt][0] = aHi[rb + g    ][kk + tt];
                ah[mt][1] = aHi[rb + g + 8][kk + tt];
                ah[mt][2] = aHi[rb + g    ][kk + tt + 4];
                ah[mt][3] = aHi[rb + g + 8][kk + tt + 4];
                al[mt][0] = aLo[rb + g    ][kk + tt];
                al[mt][1] = aLo[rb + g + 8][kk + tt];
                al[mt][2] = aLo[rb + g    ][kk + tt + 4];
                al[mt][3] = aLo[rb + g + 8][kk + tt + 4];
            }
            #pragma unroll
            for (int nt = 0; nt < 4; nt++) {
                int cb = cn + nt * 8;
                unsigned bh0 = wHiT[cb + g][kk + tt];
                unsigned bh1 = wHiT[cb + g][kk + tt + 4];
                unsigned bl0 = wLoT[cb + g][kk + tt];
                unsigned bl1 = wLoT[cb + g][kk + tt + 4];
                #pragma unroll
                for (int mt = 0; mt < 2; mt++) {
                    mma_tf32(acc[mt][nt], ah[mt][0], ah[mt][1], ah[mt][2], ah[mt][3], bh0, bh1);
                    mma_tf32(acc[mt][nt], al[mt][0], al[mt][1], al[mt][2], al[mt][3], bh0, bh1);
                    mma_tf32(acc[mt][nt], ah[mt][0], ah[mt][1], ah[mt][2], ah[mt][3], bl0, bl1);
                }
            }
        }
    }

    // ---- epilogue ----
    #pragma unroll
    for (int mt = 0; mt < 2; mt++) {
        #pragma unroll
        for (int nt = 0; nt < 4; nt++) {
            int col = cn + nt * 8 + 2 * tt;
            float v0 = acc[mt][nt][0], v1 = acc[mt][nt][1];
            float v2 = acc[mt][nt][2], v3 = acc[mt][nt][3];
            if (BNRELU) {
                float s0 = s[col], s1 = s[col + 1];
                float t0 = t[col], t1 = t[col + 1];
                v0 = fmaxf(fmaf(v0, s0, t0), 0.f);
                v1 = fmaxf(fmaf(v1, s1, t1), 0.f);
                v2 = fmaxf(fmaf(v2, s0, t0), 0.f);
                v3 = fmaxf(fmaf(v3, s1, t1), 0.f);
            }
            int r0 = rowBase + rm + mt * 16 + g;
            int r1 = r0 + 8;
            if (r0 < M) *(float2*)&out[(size_t)r0 * H + col] = make_float2(v0, v1);
            if (r1 < M) *(float2*)&out[(size_t)r1 * H + col] = make_float2(v2, v3);
        }
    }
}

// ---------------------------------------------------------------------------
// GCN aggregation (atomic-free, CSR by destination):
//   out[c] = relu( (sum_{e: col=c} hw[row_e]*dinv[row_e] + hw[c]*dinv[c]) * dinv[c] + b )
// One warp per node; lane owns features {lane, lane+32}. Edge loop batched by 4.
// ---------------------------------------------------------------------------
__global__ void __launch_bounds__(256)
aggregate_kernel(const float* __restrict__ hw, const int* __restrict__ ptr,
                 const int* __restrict__ cnt, const int* __restrict__ srow,
                 const float* __restrict__ dinv, const float* __restrict__ bias,
                 float* __restrict__ out, int n) {
    int warpId = (blockIdx.x * blockDim.x + threadIdx.x) >> 5;
    int lane = threadIdx.x & 31;
    if (warpId >= n) return;
    int nd = warpId;
    float dn = dinv[nd];
    float acc0 = hw[nd * H + lane]      * dn;   // self loop
    float acc1 = hw[nd * H + 32 + lane] * dn;

    int st = ptr[nd], en = st + cnt[nd];
    int i = st;
    for (; i + 4 <= en; i += 4) {
        int r0 = srow[i], r1 = srow[i + 1], r2 = srow[i + 2], r3 = srow[i + 3];
        float w0 = dinv[r0], w1 = dinv[r1], w2 = dinv[r2], w3 = dinv[r3];
        float a0 = hw[r0 * H + lane],      b0 = hw[r0 * H + 32 + lane];
        float a1 = hw[r1 * H + lane],      b1 = hw[r1 * H + 32 + lane];
        float a2 = hw[r2 * H + lane],      b2 = hw[r2 * H + 32 + lane];
        float a3 = hw[r3 * H + lane],      b3 = hw[r3 * H + 32 + lane];
        acc0 = fmaf(a0, w0, acc0); acc1 = fmaf(b0, w0, acc1);
        acc0 = fmaf(a1, w1, acc0); acc1 = fmaf(b1, w1, acc1);
        acc0 = fmaf(a2, w2, acc0); acc1 = fmaf(b2, w2, acc1);
        acc0 = fmaf(a3, w3, acc0); acc1 = fmaf(b3, w3, acc1);
    }
    for (; i < en; i++) {
        int r = srow[i];
        float w = dinv[r];
        acc0 = fmaf(hw[r * H + lane],      w, acc0);
        acc1 = fmaf(hw[r * H + 32 + lane], w, acc1);
    }
    out[nd * H + lane]      = fmaxf(fmaf(acc0, dn, bias[lane]),      0.f);
    out[nd * H + 32 + lane] = fmaxf(fmaf(acc1, dn, bias[lane + 32]), 0.f);
}

// ---------------------------------------------------------------------------
// Edge predictor: per edge  z = Pr[row] + Pc[col];  a = relu(z*s + t);
//                 pred = sigmoid(dot(a, w2) + b2)
// ---------------------------------------------------------------------------
__global__ void __launch_bounds__(256)
edge_kernel(const float* __restrict__ Pr, const float* __restrict__ Pc,
            const int* __restrict__ row, const int* __restrict__ col,
            const float* __restrict__ s, const float* __restrict__ t,
            const float* __restrict__ w2, const float* __restrict__ b2,
            float* __restrict__ out, int e) {
    int lane = threadIdx.x & 31;
    int warp = (blockIdx.x * blockDim.x + threadIdx.x) >> 5;
    int nwarps = (gridDim.x * blockDim.x) >> 5;

    float s0 = s[lane], s1 = s[lane + 32];
    float t0 = t[lane], t1 = t[lane + 32];
    float u0 = w2[lane], u1 = w2[lane + 32];
    float bb = b2[0];

    for (int ei = warp; ei < e; ei += nwarps) {
        int r = row[ei], c = col[ei];
        float z0 = Pr[r * H + lane]      + Pc[c * H + lane];
        float z1 = Pr[r * H + 32 + lane] + Pc[c * H + 32 + lane];
        float a0 = fmaxf(fmaf(z0, s0, t0), 0.f);
        float a1 = fmaxf(fmaf(z1, s1, t1), 0.f);
        float p = fmaf(a1, u1, a0 * u0);
        #pragma unroll
        for (int o = 16; o > 0; o >>= 1)
            p += __shfl_down_sync(0xffffffffu, p, o);
        if (lane == 0)
            out[ei] = 1.f / (1.f + __expf(-(p + bb)));
    }
}

// ---------------------------------------------------------------------------
// Launch sequence. Setup chain forked onto a side stream (capture-legal
// event fork/join) so it overlaps the enc/conv1 GEMMs; joined before the
// first aggregate which consumes ptr/cnt/srow/dinv.
// ---------------------------------------------------------------------------
extern "C" void kernel_launch(void* const* d_in, const int* in_sizes, int n_in,
                              void* d_out, int out_size) {
    const float* x        = (const float*)d_in[0];
    const int*   eidx     = (const int*)  d_in[1];
    const float* enc_W    = (const float*)d_in[2];
    const float* enc_b    = (const float*)d_in[3];
    const float* enc_g    = (const float*)d_in[4];
    const float* enc_beta = (const float*)d_in[5];
    const float* enc_mean = (const float*)d_in[6];
    const float* enc_var  = (const float*)d_in[7];
    const float* conv1_W  = (const float*)d_in[8];
    const float* conv1_b  = (const float*)d_in[9];
    const float* conv2_W  = (const float*)d_in[10];
    const float* conv2_b  = (const float*)d_in[11];
    const float* ep1_W    = (const float*)d_in[12];
    const float* ep1_b    = (const float*)d_in[13];
    const float* ep_g     = (const float*)d_in[14];
    const float* ep_beta  = (const float*)d_in[15];
    const float* ep_mean  = (const float*)d_in[16];
    const float* ep_var   = (const float*)d_in[17];
    const float* ep2_W    = (const float*)d_in[18];
    const float* ep2_b    = (const float*)d_in[19];

    int n = in_sizes[0] / 128;   // nodes
    int e = in_sizes[1] / 2;     // edges
    const int* row = eidx;
    const int* col = eidx + e;
    float* out = (float*)d_out;

    // Resolve scratch symbols (pure lookups; capture-safe)
    float *bufA, *bufB, *dinv, *enc_s, *enc_t, *ep_s, *ep_t;
    int *cnt, *fill, *ptr, *srow, *bsum, *boff;
    cudaGetSymbolAddress((void**)&bufA, g_bufA);
    cudaGetSymbolAddress((void**)&bufB, g_bufB);
    cudaGetSymbolAddress((void**)&cnt,  g_cnt);
    cudaGetSymbolAddress((void**)&fill, g_fill);
    cudaGetSymbolAddress((void**)&ptr,  g_ptr);
    cudaGetSymbolAddress((void**)&srow, g_srow);
    cudaGetSymbolAddress((void**)&dinv, g_dinv);
    cudaGetSymbolAddress((void**)&bsum, g_bsum);
    cudaGetSymbolAddress((void**)&boff, g_boff);
    cudaGetSymbolAddress((void**)&enc_s, g_enc_s);
    cudaGetSymbolAddress((void**)&enc_t, g_enc_t);
    cudaGetSymbolAddress((void**)&ep_s, g_ep_s);
    cudaGetSymbolAddress((void**)&ep_t, g_ep_t);

    // Side stream + events created once on the (non-captured) correctness call
    static cudaStream_t s2 = nullptr;
    static cudaEvent_t evFork = nullptr, evJoin = nullptr;
    if (s2 == nullptr) {
        cudaStreamCreateWithFlags(&s2, cudaStreamNonBlocking);
        cudaEventCreateWithFlags(&evFork, cudaEventDisableTiming);
        cudaEventCreateWithFlags(&evJoin, cudaEventDisableTiming);
    }

    int nB256 = (n + 255) / 256;
    int eB256 = (e + 255) / 256;
    int nb    = (n + 1023) / 1024;
    int gemmB = (n + GTM - 1) / GTM;

    // --- fork: CSR/degree setup on s2, overlapping GEMM chain on legacy ---
    cudaEventRecord(evFork, 0);
    cudaStreamWaitEvent(s2, evFork, 0);

    zero_kernel<<<nB256, 256, 0, s2>>>(cnt, fill, n);
    hist_kernel<<<eB256, 256, 0, s2>>>(col, cnt, e);
    scan1<<<nb, 1024, 0, s2>>>(cnt, ptr, bsum, dinv, n);
    scan2<<<1, 128, 0, s2>>>(bsum, boff, nb);
    scan3<<<nB256, 256, 0, s2>>>(ptr, boff, n);
    fill_kernel<<<eB256, 256, 0, s2>>>(row, col, ptr, fill, srow, e);
    cudaEventRecord(evJoin, s2);

    // --- node pipeline (legacy stream) ---
    prep_consts<<<1, 64>>>(enc_b, enc_g, enc_beta, enc_mean, enc_var,
                           ep1_b, ep_g, ep_beta, ep_mean, ep_var,
                           enc_s, enc_t, ep_s, ep_t);
    // h0 = relu(bn(x @ enc_W + b))          -> bufA
    gemm_tc<128, true><<<gemmB, 256>>>(x, enc_W, bufA, enc_s, enc_t, n);
    // hw1 = h0 @ conv1_W                     -> bufB
    gemm_tc<64, false><<<gemmB, 256>>>(bufA, conv1_W, bufB, nullptr, nullptr, n);

    // join: aggregates need ptr/cnt/srow/dinv
    cudaStreamWaitEvent(0, evJoin, 0);

    // h1 = relu(aggregate(hw1) + b1)         -> bufA
    aggregate_kernel<<<(n * 32 + 255) / 256, 256>>>(bufB, ptr, cnt, srow, dinv, conv1_b, bufA, n);
    // hw2 = h1 @ conv2_W                     -> bufB
    gemm_tc<64, false><<<gemmB, 256>>>(bufA, conv2_W, bufB, nullptr, nullptr, n);
    // h2 = relu(aggregate(hw2) + b2)         -> d_out[0 : n*64]  (node_embeddings)
    aggregate_kernel<<<(n * 32 + 255) / 256, 256>>>(bufB, ptr, cnt, srow, dinv, conv2_b, out, n);

    // --- edge predictor (restructured: concat-GEMM -> per-node projections) ---
    // Pr = h2 @ ep1_W[0:64]   -> bufA ;  Pc = h2 @ ep1_W[64:128] -> bufB
    gemm_tc<64, false><<<gemmB, 256>>>(out, ep1_W,          bufA, nullptr, nullptr, n);
    gemm_tc<64, false><<<gemmB, 256>>>(out, ep1_W + 64 * H, bufB, nullptr, nullptr, n);
    // pred[e] = sigmoid(dot(relu((Pr[row]+Pc[col])*s + t), w2) + b2) -> d_out[n*64 : ]
    edge_kernel<<<1184, 256>>>(bufA, bufB, row, col, ep_s, ep_t, ep2_W, ep2_b,
                               out + (size_t)n * H, e);
}